// round 12
// baseline (speedup 1.0000x reference)
#include <cuda_runtime.h>

// y = x*2 + 5 - 3/(1+x), elementwise over 8192*8192 fp32 (64M elems).
// R12: winning shape (V=4 float4/thread front-batched, T=256, 16384 CTAs,
// __stcs stores, __fdividef) with ld.global.cg loads — L2-only caching,
// no L1 allocation. Streaming data never re-hits L1 (flushed per launch,
// 0% hit rate), so skipping the L1 fill path frees L1tex wavefront slots
// shared with the store stream. Last unmeasured cache-op combination.

constexpr int V = 4;    // float4 per thread
constexpr int T = 256;  // threads per block

__device__ __forceinline__ float4 ldg_cg(const float4* p) {
    float4 v;
    asm volatile("ld.global.cg.v4.f32 {%0,%1,%2,%3}, [%4];"
                 : "=f"(v.x), "=f"(v.y), "=f"(v.z), "=f"(v.w)
                 : "l"(p));
    return v;
}

__global__ __launch_bounds__(T)
void elementwise_cg_kernel(const float4* __restrict__ in,
                           float4* __restrict__ out) {
    int base = blockIdx.x * (T * V) + threadIdx.x;

    float4 v[V];
#pragma unroll
    for (int k = 0; k < V; k++) {
        v[k] = ldg_cg(&in[base + k * T]);   // 4 independent LDG.E.CG.128, no L1 fill
    }

#pragma unroll
    for (int k = 0; k < V; k++) {
        float4 r;
        r.x = fmaf(v[k].x, 2.0f, 5.0f) - __fdividef(3.0f, 1.0f + v[k].x);
        r.y = fmaf(v[k].y, 2.0f, 5.0f) - __fdividef(3.0f, 1.0f + v[k].y);
        r.z = fmaf(v[k].z, 2.0f, 5.0f) - __fdividef(3.0f, 1.0f + v[k].z);
        r.w = fmaf(v[k].w, 2.0f, 5.0f) - __fdividef(3.0f, 1.0f + v[k].w);
        __stcs(&out[base + k * T], r);      // evict-first streaming stores
    }
}

extern "C" void kernel_launch(void* const* d_in, const int* in_sizes, int n_in,
                              void* d_out, int out_size) {
    const float* x = (const float*)d_in[0];
    float* y = (float*)d_out;
    int n = in_sizes[0];          // 67108864 = 8192*8192
    int n4 = n >> 2;              // 16777216 float4

    // Exact tiling: 16777216 / (256*4) = 16384 blocks, no tail.
    int blocks = n4 / (T * V);
    elementwise_cg_kernel<<<blocks, T>>>(
        (const float4*)x, (float4*)y);
}